// round 16
// baseline (speedup 1.0000x reference)
#include <cuda_runtime.h>
#include <cuda_fp16.h>
#include <cstdint>

// ---------------- problem constants ----------------
#define CIN   256
#define KOUT  256
#define HH    56
#define WW    56
#define NPF   2304           // 256*3*3 per output filter
#define PH    58
#define PW    58
#define NIMG  32
#define PIX   (HH*WW)        // 3136
#define TPI   784            // 28*28 Winograd tiles per image
#define NTIL  (NIMG*TPI)     // 25088 tiles total

// ---------------- GEMM tiling (per Winograd position p) ----------------
#define MT    224            // 25088 = 224*112 exact
#define NT    64
#define KC    32             // K chunk (halfs)
#define NCH   8              // 256 / 32
#define NS    4
#define NTHR  224            // 7 warps x (32m x 64n); 2 CTAs/SM

#define ROWB  80
#define ASTG  (MT*ROWB)      // 17920
#define BSTG  (NT*ROWB)      // 5120
#define STG   (ASTG+BSTG)    // 23040
#define SMDYN (NS*STG)       // 92160  (stile 224*65*4=58240 fits)

// ---------------- device scratch ----------------
__device__ __half g_b[9 * KOUT * CIN];                   // [rs][k][c], +-1
__device__ float  g_alpha[KOUT];
__device__ __half g_xpad[(size_t)NIMG * PH * PW * CIN];  // [n][hp][wp][c]
__device__ __half g_u[16 * KOUT * CIN];                  // [p][k][c]
__device__ __half g_v[(size_t)16 * NTIL * CIN];          // [p][t][c]  205MB
__device__ __half g_m[(size_t)16 * NTIL * KOUT];         // [p][t][k]  205MB

// ---------------- ptx helpers (family-portable only) ----------------
__device__ __forceinline__ void cp16(uint32_t dst, const void* src) {
    asm volatile("cp.async.cg.shared.global [%0], [%1], 16;"
                 :: "r"(dst), "l"(__cvta_generic_to_global(src)) : "memory");
}
#define CP_COMMIT()  asm volatile("cp.async.commit_group;" ::: "memory")
#define CP_WAIT(N)   asm volatile("cp.async.wait_group %0;" :: "n"(N) : "memory")

#define LDSM4(R, addr)                                                        \
    asm volatile("ldmatrix.sync.aligned.m8n8.x4.shared.b16 {%0,%1,%2,%3}, [%4];" \
                 : "=r"((R)[0]), "=r"((R)[1]), "=r"((R)[2]), "=r"((R)[3])     \
                 : "r"(addr))

#define MMA16816(D, A, B0, B1)                                                \
    asm volatile("mma.sync.aligned.m16n8k16.row.col.f32.f16.f16.f32 "         \
                 "{%0,%1,%2,%3}, {%4,%5,%6,%7}, {%8,%9}, {%0,%1,%2,%3};"      \
                 : "+f"((D)[0]), "+f"((D)[1]), "+f"((D)[2]), "+f"((D)[3])     \
                 : "r"((A)[0]), "r"((A)[1]), "r"((A)[2]), "r"((A)[3]),        \
                   "r"(B0), "r"(B1))

// ---------------------------------------------------------------------------
// K0: ternarize (float4 + warp shuffle reductions). One block per filter.
// ---------------------------------------------------------------------------
__global__ void ternarize_kernel(const float* __restrict__ w) {
    const int o = blockIdx.x;
    const int tid = threadIdx.x;
    const int lane = tid & 31;
    const int wrp = tid >> 5;
    const float4* wo4 = (const float4*)(w + (size_t)o * NPF);
    __shared__ float red[8];
    __shared__ float s_delta;

    float s = 0.f;
    for (int i = tid; i < NPF / 4; i += 256) {
        float4 v = wo4[i];
        s += fabsf(v.x) + fabsf(v.y) + fabsf(v.z) + fabsf(v.w);
    }
    #pragma unroll
    for (int d = 16; d > 0; d >>= 1) s += __shfl_xor_sync(~0u, s, d);
    if (lane == 0) red[wrp] = s;
    __syncthreads();
    if (tid == 0) {
        float t = 0.f;
        #pragma unroll
        for (int i = 0; i < 8; i++) t += red[i];
        s_delta = (0.7f / (float)NPF) * t;
    }
    __syncthreads();
    const float delta = s_delta;

    float cnt = 0.f, asum = 0.f;
    for (int i = tid; i < NPF / 4; i += 256) {
        float4 v = wo4[i];
        float a;
        a = fabsf(v.x); if (a > delta) { cnt += 1.f; asum += a; }
        a = fabsf(v.y); if (a > delta) { cnt += 1.f; asum += a; }
        a = fabsf(v.z); if (a > delta) { cnt += 1.f; asum += a; }
        a = fabsf(v.w); if (a > delta) { cnt += 1.f; asum += a; }
    }
    #pragma unroll
    for (int d = 16; d > 0; d >>= 1) {
        cnt  += __shfl_xor_sync(~0u, cnt, d);
        asum += __shfl_xor_sync(~0u, asum, d);
    }
    if (lane == 0) red[wrp] = cnt;
    __syncthreads();
    float cnt_tot = 0.f;
    if (tid == 0) {
        #pragma unroll
        for (int i = 0; i < 8; i++) cnt_tot += red[i];
        red[0] = cnt_tot;
    }
    __syncthreads();
    cnt_tot = red[0];
    __syncthreads();
    if (lane == 0) red[wrp] = asum;
    __syncthreads();
    if (tid == 0) {
        float t = 0.f;
        #pragma unroll
        for (int i = 0; i < 8; i++) t += red[i];
        g_alpha[o] = t / cnt_tot;
    }

    const float* wo = w + (size_t)o * NPF;
    for (int i = tid; i < NPF; i += 256) {
        float v = wo[i];
        float t = (v > delta) ? 1.f : ((v < -delta) ? -1.f : 0.f);
        int c = i / 9, rs = i % 9;
        g_b[((size_t)rs * KOUT + o) * CIN + c] = __float2half_rn(t);
    }
}

// ---------------------------------------------------------------------------
// K0b: U = G g G^T  (exact multiples of 0.25). grid 256(k), 256 thr(c).
// ---------------------------------------------------------------------------
__global__ void u_transform_kernel() {
    const int k = blockIdx.x, c = threadIdx.x;
    float g[3][3];
    #pragma unroll
    for (int r = 0; r < 3; r++)
        #pragma unroll
        for (int s = 0; s < 3; s++)
            g[r][s] = __half2float(g_b[((size_t)(3 * r + s) * KOUT + k) * CIN + c]);

    float t[4][3];
    #pragma unroll
    for (int s = 0; s < 3; s++) {
        t[0][s] = g[0][s];
        t[1][s] = 0.5f * (g[0][s] + g[1][s] + g[2][s]);
        t[2][s] = 0.5f * (g[0][s] - g[1][s] + g[2][s]);
        t[3][s] = g[2][s];
    }
    #pragma unroll
    for (int i = 0; i < 4; i++) {
        float u0 = t[i][0];
        float u1 = 0.5f * (t[i][0] + t[i][1] + t[i][2]);
        float u2 = 0.5f * (t[i][0] - t[i][1] + t[i][2]);
        float u3 = t[i][2];
        g_u[((size_t)(4 * i + 0) * KOUT + k) * CIN + c] = __float2half_rn(u0);
        g_u[((size_t)(4 * i + 1) * KOUT + k) * CIN + c] = __float2half_rn(u1);
        g_u[((size_t)(4 * i + 2) * KOUT + k) * CIN + c] = __float2half_rn(u2);
        g_u[((size_t)(4 * i + 3) * KOUT + k) * CIN + c] = __float2half_rn(u3);
    }
}

// ---------------------------------------------------------------------------
// K1: pad + NCHW->NHWC transpose + fp16 convert (border rows write zeros).
// ---------------------------------------------------------------------------
__global__ void pad_transpose_kernel(const float* __restrict__ x) {
    __shared__ float s[64][57];
    const int hp = blockIdx.x, c0 = blockIdx.y * 64, n = blockIdx.z;
    __half* dst = g_xpad + ((size_t)(n * PH + hp) * PW) * CIN + c0;

    if (hp == 0 || hp == PH - 1) {
        for (int idx = threadIdx.x; idx < PW * 8; idx += 256) {
            int wp = idx >> 3, u = idx & 7;
            ((uint4*)(dst + (size_t)wp * CIN))[u] = make_uint4(0u, 0u, 0u, 0u);
        }
        return;
    }

    const int h = hp - 1;
    const float* xp = x + ((size_t)(n * CIN + c0) * HH + h) * WW;
    for (int idx = threadIdx.x; idx < 64 * WW; idx += 256) {
        int ci = idx / WW, w = idx - ci * WW;
        s[ci][w] = xp[(size_t)ci * PIX + w];
    }
    __syncthreads();

    for (int idx = threadIdx.x; idx < PW * 64; idx += 256) {
        int wp = idx / 64, ci = idx - wp * 64;
        float v = (wp >= 1 && wp <= WW) ? s[ci][wp - 1] : 0.f;
        dst[(size_t)wp * CIN + ci] = __float2half_rn(v);
    }
}

// ---------------------------------------------------------------------------
// K2: V = B^T d B per (tile, channel). grid (28 u, 4 cchunk, 32 img), 256 thr.
// d[a][b] = xpad[2u+a][2v+b][c]; smem tile [4][58][64] halfs.
// ---------------------------------------------------------------------------
__global__ void v_transform_kernel() {
    __shared__ __half sd[4 * 58 * 64];
    const int u = blockIdx.x, c0 = blockIdx.y * 64, img = blockIdx.z;
    const int tid = threadIdx.x;

    // load rows 2u..2u+3, 58 wp, 64 channels (1856 uint4)
    const __half* src = g_xpad + ((size_t)(img * PH + 2 * u) * PW) * CIN + c0;
    #pragma unroll
    for (int q = 0; q < 8; q++) {
        int idx = tid + 256 * q;
        if (q < 7 || idx < 1856) {
            int slot = idx >> 3;          // (a*58 + wp)
            int seg  = idx & 7;
            int a = slot / 58, wp = slot % 58;
            ((uint4*)sd)[slot * 8 + seg] =
                *(const uint4*)(src + ((size_t)a * PW + wp) * CIN + seg * 8);
        }
    }
    __syncthreads();

    const int c = tid & 63;
    const int vg = tid >> 6;
    #pragma unroll 1
    for (int v = vg; v < 28; v += 4) {
        float d[4][4];
        #pragma unroll
        for (int a = 0; a < 4; a++)
            #pragma unroll
            for (int b = 0; b < 4; b++)
                d[a][b] = __half2float(sd[(a * 58 + 2 * v + b) * 64 + c]);

        float t[4][4];
        #pragma unroll
        for (int b = 0; b < 4; b++) {
            t[0][b] = d[0][b] - d[2][b];
            t[1][b] = d[1][b] + d[2][b];
            t[2][b] = d[2][b] - d[1][b];
            t[3][b] = d[1][b] - d[3][b];
        }
        const size_t tt = (size_t)img * TPI + u * 28 + v;
        #pragma unroll
        for (int i = 0; i < 4; i++) {
            float V0 = t[i][0] - t[i][2];
            float V1 = t[i][1] + t[i][2];
            float V2 = t[i][2] - t[i][1];
            float V3 = t[i][1] - t[i][3];
            g_v[((size_t)(4 * i + 0) * NTIL + tt) * CIN + c0 + c] = __float2half_rn(V0);
            g_v[((size_t)(4 * i + 1) * NTIL + tt) * CIN + c0 + c] = __float2half_rn(V1);
            g_v[((size_t)(4 * i + 2) * NTIL + tt) * CIN + c0 + c] = __float2half_rn(V2);
            g_v[((size_t)(4 * i + 3) * NTIL + tt) * CIN + c0 + c] = __float2half_rn(V3);
        }
    }
}

// ---------------------------------------------------------------------------
// K3: batched GEMM  M_p[t][k] = sum_c V_p[t][c] * U_p[k][c].
// grid (112 tileblk, 4 n, 16 p) -- p slowest so V_p (12.8MB) stays L2-resident.
// CTA 224x64, 7 warps x (32m x 64n), 2 CTAs/SM, NS=4, 8 K-chunks.
// ---------------------------------------------------------------------------
__global__ void __launch_bounds__(NTHR, 2)
wino_gemm_kernel() {
    extern __shared__ __align__(128) char smem[];
    const uint32_t sb = (uint32_t)__cvta_generic_to_shared(smem);

    const int tid = threadIdx.x;
    const int lane = tid & 31;
    const int wid = tid >> 5;            // 0..6
    const int t0 = blockIdx.x * MT;
    const int n0 = blockIdx.y * NT;
    const int p  = blockIdx.z;

    // ---- cp.async precompute: A 224 rows x 4 segs = 896 slots / 224 thr ----
    const __half* a_g[4];
    uint32_t sa_off[4];
    #pragma unroll
    for (int q = 0; q < 4; q++) {
        int slot = tid + NTHR * q;
        int row = slot >> 2, seg = slot & 3;
        a_g[q] = g_v + ((size_t)p * NTIL + t0 + row) * CIN + seg * 8;
        sa_off[q] = (uint32_t)(row * ROWB + seg * 16);
    }
    // B: 64 rows x 4 segs = 256 slots: q0 all 224, q1 tid<32
    const __half* b_g[2];
    uint32_t sb_off[2];
    #pragma unroll
    for (int q = 0; q < 2; q++) {
        int slot = tid + NTHR * q; if (slot >= 256) slot = 0;
        int row = slot >> 2, seg = slot & 3;
        b_g[q] = g_u + ((size_t)p * KOUT + n0 + row) * CIN + seg * 8;
        sb_off[q] = (uint32_t)(row * ROWB + seg * 16);
    }
    const bool bq1 = (tid < 32);

    // ---- ldmatrix addresses ----
    uint32_t a_lm[2];
    #pragma unroll
    for (int i = 0; i < 2; i++)
        a_lm[i] = (uint32_t)((wid * 32 + i * 16 + (lane & 15)) * ROWB
                             + (lane >> 4) * 16);
    uint32_t b_lm[4];
    {
        int nn = (lane & 7) + ((lane & 16) >> 1);
        int kk0 = lane & 8;
        #pragma unroll
        for (int j = 0; j < 4; j++)
            b_lm[j] = (uint32_t)((j * 16 + nn) * ROWB + kk0 * 2);
    }

    float acc[2][8][4];
    #pragma unroll
    for (int i = 0; i < 2; i++)
        #pragma unroll
        for (int j = 0; j < 8; j++)
            #pragma unroll
            for (int r = 0; r < 4; r++) acc[i][j][r] = 0.f;

    auto fill = [&](int st, int ch) {
        size_t off = (size_t)ch * KC;
        uint32_t ab = sb + st * STG;
        uint32_t bb = ab + ASTG;
        #pragma unroll
        for (int q = 0; q < 4; q++) cp16(ab + sa_off[q], a_g[q] + off);
        cp16(bb + sb_off[0], b_g[0] + off);
        if (bq1) cp16(bb + sb_off[1], b_g[1] + off);
        CP_COMMIT();
    };

    fill(0, 0); fill(1, 1); fill(2, 2);

    int st = 0;
    #pragma unroll 1
    for (int ch = 0; ch < NCH; ch++) {
        CP_WAIT(2);
        __syncthreads();
        if (ch + 3 < NCH) fill((st + 3) & (NS - 1), ch + 3);
        else              CP_COMMIT();

        uint32_t ab = sb + st * STG;
        uint32_t bb = ab + ASTG;
        uint32_t a[2][2][4], b[2][4][4];
        #pragma unroll
        for (int kk = 0; kk < 2; kk++) {
            #pragma unroll
            for (int i = 0; i < 2; i++) LDSM4(a[kk][i], ab + a_lm[i] + kk * 32);
            #pragma unroll
            for (int j = 0; j < 4; j++) LDSM4(b[kk][j], bb + b_lm[j] + kk * 32);
            #pragma unroll
            for (int i = 0; i < 2; i++)
                #pragma unroll
                for (int j = 0; j < 8; j++)
                    MMA16816(acc[i][j], a[kk][i],
                             b[kk][j >> 1][(j & 1) * 2],
                             b[kk][j >> 1][(j & 1) * 2 + 1]);
        }
        st = (st + 1) & (NS - 1);
    }
    __syncthreads();

    // ---- epilogue: stage fp32 in smem, write fp16 M (k-contiguous) ----
    float* stile = (float*)smem;   // [224][65] = 58.2KB
    #pragma unroll
    for (int i = 0; i < 2; i++)
        #pragma unroll
        for (int j = 0; j < 8; j++) {
            int no = j * 8 + (lane & 3) * 2;
            int m0 = wid * 32 + i * 16 + (lane >> 2);
            stile[m0 * 65 + no]           = acc[i][j][0];
            stile[m0 * 65 + no + 1]       = acc[i][j][1];
            stile[(m0 + 8) * 65 + no]     = acc[i][j][2];
            stile[(m0 + 8) * 65 + no + 1] = acc[i][j][3];
        }
    __syncthreads();

    __half2* dst = (__half2*)(g_m + ((size_t)p * NTIL + t0 + tid) * KOUT + n0);
    #pragma unroll
    for (int k2 = 0; k2 < 32; k2++)
        dst[k2] = __floats2half2_rn(stile[tid * 65 + 2 * k2],
                                    stile[tid * 65 + 2 * k2 + 1]);
}

// ---------------------------------------------------------------------------
// K4: inverse transform Y = A^T M A, out = alpha*Y + bias.
// grid (28 u, 32 img, 4 kchunk), 256 thr. Stage via smem for coalesced NCHW.
// ---------------------------------------------------------------------------
__global__ void inverse_kernel(const float* __restrict__ bias_g,
                               float* __restrict__ out) {
    __shared__ float ytile[2 * 64 * 57];   // [y][k][w padded 57] = 29.2KB
    __shared__ float s_alpha[64], s_bias[64];
    const int u = blockIdx.x, img = blockIdx.y, k0 = blockIdx.z * 64;
    const int tid = threadIdx.x;

    if (tid < 64)             s_alpha[tid] = g_alpha[k0 + tid];
    else if (tid < 128)       s_bias[tid - 64] = bias_g[k0 + tid - 64];
    __syncthreads();

    const int k = tid & 63;
    const int vg = tid >> 6;
    const float al = s_alpha[k], bi = s_bias[k];

    #pragma unroll 1
    for (int v = vg; v < 28; v += 4) {
        const size_t tt = (size_t)img * TPI + u * 28 + v;
        float M[16];
        #pragma unroll
        for (int pp = 0; pp < 16; pp++)
            M[pp] = __half2float(g_m[((size_t)pp * NTIL + tt) * KOUT + k0 + k]);

        float ty[2][4];
        #pragma unroll
        for (int j = 0; j < 4; j++) {
            ty[0][j] = M[j] + M[4 + j] + M[8 + j];
            ty[1][j] = M[4 + j] - M[8 + j] - M[12 + j];
        }
        #pragma unroll
        for (int y = 0; y < 2; y++) {
            float Y0 = ty[y][0] + ty[y][1] + ty[y][2];
            float Y1 = ty[y][1] - ty[y][2] - ty[y][3];
            ytile[(y * 64 + k) * 57 + 2 * v]     = fmaf(al, Y0, bi);
            ytile[(y * 64 + k) * 57 + 2 * v + 1] = fmaf(al, Y1, bi);
        }
    }
    __syncthreads();

    // write 2 rows x 64 k x 56 w = 7168 floats, coalesced (w fast)
    float* ob = out + ((size_t)img * KOUT + k0) * PIX + (2 * u) * WW;
    #pragma unroll
    for (int q = 0; q < 28; q++) {
        int idx = tid + 256 * q;
        int kk = idx / 112;
        int rem = idx - kk * 112;
        int y = rem / 56, w = rem - y * 56;
        ob[(size_t)kk * PIX + y * WW + w] = ytile[(y * 64 + kk) * 57 + w];
    }
}

// ---------------------------------------------------------------------------
extern "C" void kernel_launch(void* const* d_in, const int* in_sizes, int n_in,
                              void* d_out, int out_size) {
    const float* x      = (const float*)d_in[0];
    const float* weight = (const float*)d_in[1];
    const float* bias   = (const float*)d_in[2];
    float* out          = (float*)d_out;

    cudaFuncSetAttribute(wino_gemm_kernel,
                         cudaFuncAttributeMaxDynamicSharedMemorySize, SMDYN);

    ternarize_kernel<<<KOUT, 256>>>(weight);
    u_transform_kernel<<<KOUT, 256>>>();
    pad_transpose_kernel<<<dim3(PH, 4, NIMG), 256>>>(x);
    v_transform_kernel<<<dim3(28, 4, NIMG), 256>>>();
    wino_gemm_kernel<<<dim3(NTIL / MT, KOUT / NT, 16), NTHR, SMDYN>>>();
    inverse_kernel<<<dim3(28, NIMG, 4), 256>>>(bias, out);
}

// round 17
// speedup vs baseline: 1.6351x; 1.6351x over previous
#include <cuda_runtime.h>
#include <cuda_fp16.h>
#include <cstdint>

// ---------------- problem constants ----------------
#define CIN   256
#define KOUT  256
#define HH    56
#define WW    56
#define NPF   2304           // 256*3*3 per output filter
#define PH    58
#define PW    58
#define NIMG  32
#define PIX   (HH*WW)        // 3136
#define MTOT  (NIMG*PIX)     // 100352

// ---------------- tiling ----------------
#define MT    224            // = 4*56: every tile row-aligned, 448 tiles exact
#define NT    64             // CTA N tile
#define NTHR  224            // 7 warps, each 32(m) x 64(n); 2 CTAs/SM

// A stage: 6 input rows x 58 wp x 64B payload @80B stride (conflict-free)
#define AROW  80
#define AST   (6*58*AROW)    // 27840
// B sub-stage: 3 taps x 64 n-rows x 64B @80B stride
#define BST   (3*64*AROW)    // 15360
#define SMDYN (2*AST + 3*BST)  // 101760 (stile 224*65*4=58240 fits)

// ---------------- device scratch ----------------
__device__ __half g_b[9 * KOUT * CIN];                   // [rs][k][c], +-1
__device__ float  g_alpha[KOUT];
__device__ __half g_xpad[(size_t)NIMG * PH * PW * CIN];  // [n][hp][wp][c]

// ---------------- ptx helpers (family-portable only) ----------------
__device__ __forceinline__ void cp16(uint32_t dst, const void* src) {
    asm volatile("cp.async.cg.shared.global [%0], [%1], 16;"
                 :: "r"(dst), "l"(__cvta_generic_to_global(src)) : "memory");
}
#define CP_COMMIT()  asm volatile("cp.async.commit_group;" ::: "memory")
#define CP_WAIT(N)   asm volatile("cp.async.wait_group %0;" :: "n"(N) : "memory")

#define LDSM4(R, addr)                                                        \
    asm volatile("ldmatrix.sync.aligned.m8n8.x4.shared.b16 {%0,%1,%2,%3}, [%4];" \
                 : "=r"((R)[0]), "=r"((R)[1]), "=r"((R)[2]), "=r"((R)[3])     \
                 : "r"(addr))

#define MMA16816(D, A, B0, B1)                                                \
    asm volatile("mma.sync.aligned.m16n8k16.row.col.f32.f16.f16.f32 "         \
                 "{%0,%1,%2,%3}, {%4,%5,%6,%7}, {%8,%9}, {%0,%1,%2,%3};"      \
                 : "+f"((D)[0]), "+f"((D)[1]), "+f"((D)[2]), "+f"((D)[3])     \
                 : "r"((A)[0]), "r"((A)[1]), "r"((A)[2]), "r"((A)[3]),        \
                   "r"(B0), "r"(B1))

// ---------------------------------------------------------------------------
// K0: ternarize (float4 + warp shuffle reductions). One block per filter.
// ---------------------------------------------------------------------------
__global__ void ternarize_kernel(const float* __restrict__ w) {
    const int o = blockIdx.x;
    const int tid = threadIdx.x;
    const int lane = tid & 31;
    const int wrp = tid >> 5;
    const float4* wo4 = (const float4*)(w + (size_t)o * NPF);
    __shared__ float red[8];
    __shared__ float s_delta;

    float s = 0.f;
    for (int i = tid; i < NPF / 4; i += 256) {
        float4 v = wo4[i];
        s += fabsf(v.x) + fabsf(v.y) + fabsf(v.z) + fabsf(v.w);
    }
    #pragma unroll
    for (int d = 16; d > 0; d >>= 1) s += __shfl_xor_sync(~0u, s, d);
    if (lane == 0) red[wrp] = s;
    __syncthreads();
    if (tid == 0) {
        float t = 0.f;
        #pragma unroll
        for (int i = 0; i < 8; i++) t += red[i];
        s_delta = (0.7f / (float)NPF) * t;
    }
    __syncthreads();
    const float delta = s_delta;

    float cnt = 0.f, asum = 0.f;
    for (int i = tid; i < NPF / 4; i += 256) {
        float4 v = wo4[i];
        float a;
        a = fabsf(v.x); if (a > delta) { cnt += 1.f; asum += a; }
        a = fabsf(v.y); if (a > delta) { cnt += 1.f; asum += a; }
        a = fabsf(v.z); if (a > delta) { cnt += 1.f; asum += a; }
        a = fabsf(v.w); if (a > delta) { cnt += 1.f; asum += a; }
    }
    #pragma unroll
    for (int d = 16; d > 0; d >>= 1) {
        cnt  += __shfl_xor_sync(~0u, cnt, d);
        asum += __shfl_xor_sync(~0u, asum, d);
    }
    if (lane == 0) red[wrp] = cnt;
    __syncthreads();
    float cnt_tot = 0.f;
    if (tid == 0) {
        #pragma unroll
        for (int i = 0; i < 8; i++) cnt_tot += red[i];
        red[0] = cnt_tot;
    }
    __syncthreads();
    cnt_tot = red[0];
    __syncthreads();
    if (lane == 0) red[wrp] = asum;
    __syncthreads();
    if (tid == 0) {
        float t = 0.f;
        #pragma unroll
        for (int i = 0; i < 8; i++) t += red[i];
        g_alpha[o] = t / cnt_tot;
    }

    const float* wo = w + (size_t)o * NPF;
    for (int i = tid; i < NPF; i += 256) {
        float v = wo[i];
        float t = (v > delta) ? 1.f : ((v < -delta) ? -1.f : 0.f);
        int c = i / 9, rs = i % 9;
        g_b[((size_t)rs * KOUT + o) * CIN + c] = __float2half_rn(t);
    }
}

// ---------------------------------------------------------------------------
// K1: pad + NCHW->NHWC transpose + fp16 convert (border rows write zeros).
// ---------------------------------------------------------------------------
__global__ void pad_transpose_kernel(const float* __restrict__ x) {
    __shared__ float s[64][57];
    const int hp = blockIdx.x, c0 = blockIdx.y * 64, n = blockIdx.z;
    __half* dst = g_xpad + ((size_t)(n * PH + hp) * PW) * CIN + c0;

    if (hp == 0 || hp == PH - 1) {
        for (int idx = threadIdx.x; idx < PW * 8; idx += 256) {
            int wp = idx >> 3, u = idx & 7;
            ((uint4*)(dst + (size_t)wp * CIN))[u] = make_uint4(0u, 0u, 0u, 0u);
        }
        return;
    }

    const int h = hp - 1;
    const float* xp = x + ((size_t)(n * CIN + c0) * HH + h) * WW;
    for (int idx = threadIdx.x; idx < 64 * WW; idx += 256) {
        int ci = idx / WW, w = idx - ci * WW;
        s[ci][w] = xp[(size_t)ci * PIX + w];
    }
    __syncthreads();

    for (int idx = threadIdx.x; idx < PW * 64; idx += 256) {
        int wp = idx / 64, ci = idx - wp * 64;
        float v = (wp >= 1 && wp <= WW) ? s[ci][wp - 1] : 0.f;
        dst[(size_t)wp * CIN + ci] = __float2half_rn(v);
    }
}

// ---------------------------------------------------------------------------
// K2: implicit-GEMM conv, 2D-halo A reuse across all 9 taps.
// Grid (448, 4): CTA = 224 pixels x 64 chans. 7 warps, each 32(m) x 64(n).
// 24 groups (8 cc x 3 tap-rows). B ring of 3, one commit per group,
// CP_WAIT(1): every fill gets TWO compute periods to land.
// ---------------------------------------------------------------------------
__global__ void __launch_bounds__(NTHR, 2)
conv_mma_kernel(const float* __restrict__ bias_g, float* __restrict__ out) {
    extern __shared__ __align__(128) char smem[];
    const uint32_t sb = (uint32_t)__cvta_generic_to_shared(smem);

    const int tid = threadIdx.x;
    const int lane = tid & 31;
    const int wid = tid >> 5;              // 0..6

    const int p0 = blockIdx.x * MT;        // p0 % 56 == 0, same image
    const int n0 = blockIdx.y * NT;
    const int nimg = p0 / PIX;
    const int h0 = (p0 - nimg * PIX) / WW; // in {0,4,...,52}

    __shared__ float s_alpha[NT], s_bias[NT];
    if (tid < NT)              s_alpha[tid] = g_alpha[n0 + tid];
    else if (tid < 2 * NT)     s_bias[tid - NT] = bias_g[n0 + tid - NT];

    // ---- A fill precompute: 6 slots x 58 wp x 4 segs = 1392 cp16 ----
    const __half* af_src[7];
    uint32_t af_dst[7];
    #pragma unroll
    for (int q = 0; q < 7; q++) {
        int idx = tid + NTHR * q; if (idx >= 1392) idx = 0;
        int slot = idx / 232, rem = idx % 232;
        int wp = rem >> 2, seg = rem & 3;
        af_src[q] = g_xpad + ((size_t)((nimg * PH + (h0 + slot)) * PW + wp)) * CIN
                  + seg * 8;
        af_dst[q] = (uint32_t)(slot * 4640 + wp * AROW + seg * 16);
    }
    // ---- B fill precompute: 3 taps x 64 rows x 4 segs = 768 cp16 ----
    const __half* bf_src[4];
    uint32_t bf_dst[4];
    #pragma unroll
    for (int q = 0; q < 4; q++) {
        int idx = tid + NTHR * q; if (idx >= 768) idx = 0;
        int tap = idx >> 8, rem = idx & 255;
        int row = rem >> 2, seg = rem & 3;
        bf_src[q] = g_b + (size_t)tap * (KOUT * CIN) + (size_t)(n0 + row) * CIN
                  + seg * 8;
        bf_dst[q] = (uint32_t)(tap * 5120 + row * AROW + seg * 16);
    }

    // ---- ldmatrix address precompute ----
    uint32_t a_lm[2];
    #pragma unroll
    for (int i = 0; i < 2; i++) {
        int m = wid * 32 + i * 16 + (lane & 15);
        int j = m / 56, w = m - j * 56;
        a_lm[i] = (uint32_t)(j * 4640 + w * AROW + (lane >> 4) * 16);
    }
    uint32_t b_lm[4];
    {
        int nn = (lane & 7) + ((lane & 16) >> 1);
        int kk0 = lane & 8;
        #pragma unroll
        for (int j = 0; j < 4; j++)
            b_lm[j] = (uint32_t)((j * 16 + nn) * AROW + kk0 * 2);
    }

    float acc[2][8][4];
    #pragma unroll
    for (int i = 0; i < 2; i++)
        #pragma unroll
        for (int j = 0; j < 8; j++)
            #pragma unroll
            for (int r = 0; r < 4; r++) acc[i][j][r] = 0.f;

    auto fillA = [&](int buf, int cc) {
        uint32_t base = sb + buf * AST;
        #pragma unroll
        for (int q = 0; q < 7; q++)
            if (q < 6 || tid < 1392 - 6 * NTHR)
                cp16(base + af_dst[q], af_src[q] + cc * 32);
    };
    auto fillB = [&](int slot, int g, int cc) {
        uint32_t base = sb + 2 * AST + slot * BST;
        size_t off = (size_t)(3 * g) * (KOUT * CIN) + cc * 32;
        #pragma unroll
        for (int q = 0; q < 4; q++)
            if (q < 3 || tid < 768 - 3 * NTHR)
                cp16(base + bf_dst[q], bf_src[q] + off);
    };

    // ---- prologue: commits for groups G=0 and G=1 ----
    fillA(0, 0); fillB(0, 0, 0); CP_COMMIT();   // C_{-2}: data for G=0
    fillB(1, 1, 0); CP_COMMIT();                // C_{-1}: data for G=1

    // ---- mainloop over 24 groups: G = cc*3 + g ----
    #pragma unroll 1
    for (int G = 0; G < 24; G++) {
        const int cc = G / 3, g = G - cc * 3;

        CP_WAIT(1);          // group G's fill done; G+1's may still fly
        __syncthreads();

        // issue fill for group G+2 (one commit per iteration, may be empty)
        {
            int G2 = G + 2;
            if (G2 < 24) {
                int cc2 = G2 / 3, g2 = G2 - cc2 * 3;
                if (g2 == 0) fillA(cc2 & 1, cc2);   // A for cc2: 2 barriers early
                fillB(G2 % 3, g2, cc2);
            }
            CP_COMMIT();
        }

        uint32_t ab = sb + (cc & 1) * AST;
        uint32_t bb = sb + 2 * AST + (G % 3) * BST;
        #pragma unroll
        for (int t = 0; t < 3; t++) {
            uint32_t aoff = (uint32_t)(g * 4640 + t * AROW);
            uint32_t boff = (uint32_t)(t * 5120);
            uint32_t a[2][2][4], b[2][4][4];
            #pragma unroll
            for (int kk = 0; kk < 2; kk++) {
                #pragma unroll
                for (int i = 0; i < 2; i++)
                    LDSM4(a[kk][i], ab + a_lm[i] + aoff + kk * 32);
                #pragma unroll
                for (int j = 0; j < 4; j++)
                    LDSM4(b[kk][j], bb + boff + b_lm[j] + kk * 32);
                #pragma unroll
                for (int i = 0; i < 2; i++)
                    #pragma unroll
                    for (int j = 0; j < 8; j++)
                        MMA16816(acc[i][j], a[kk][i],
                                 b[kk][j >> 1][(j & 1) * 2],
                                 b[kk][j >> 1][(j & 1) * 2 + 1]);
            }
        }
    }
    CP_WAIT(0);
    __syncthreads();

    // ---- epilogue: stage through smem, out = alpha*acc + bias ----
    float* stile = (float*)smem;   // [224][65] = 58.2KB <= 101.8KB dyn
    #pragma unroll
    for (int i = 0; i < 2; i++)
        #pragma unroll
        for (int j = 0; j < 8; j++) {
            int no = j * 8 + (lane & 3) * 2;
            int m0 = wid * 32 + i * 16 + (lane >> 2);
            stile[m0 * 65 + no]           = acc[i][j][0];
            stile[m0 * 65 + no + 1]       = acc[i][j][1];
            stile[(m0 + 8) * 65 + no]     = acc[i][j][2];
            stile[(m0 + 8) * 65 + no + 1] = acc[i][j][3];
        }
    __syncthreads();

    const int p = p0 + tid;                 // always < MTOT (exact tiling)
    const int hw = p - nimg * PIX;
    float* ob = out + ((size_t)nimg * KOUT + n0) * PIX + hw;
    #pragma unroll
    for (int k = 0; k < NT; k++) {
        float v = stile[tid * 65 + k];
        ob[(size_t)k * PIX] = fmaf(s_alpha[k], v, s_bias[k]);
    }
}

// ---------------------------------------------------------------------------
extern "C" void kernel_launch(void* const* d_in, const int* in_sizes, int n_in,
                              void* d_out, int out_size) {
    const float* x      = (const float*)d_in[0];
    const float* weight = (const float*)d_in[1];
    const float* bias   = (const float*)d_in[2];
    float* out          = (float*)d_out;

    cudaFuncSetAttribute(conv_mma_kernel,
                         cudaFuncAttributeMaxDynamicSharedMemorySize, SMDYN);

    ternarize_kernel<<<KOUT, 256>>>(weight);
    pad_transpose_kernel<<<dim3(PH, 4, NIMG), 256>>>(x);
    conv_mma_kernel<<<dim3(MTOT / MT, KOUT / NT), NTHR, SMDYN>>>(bias, out);
}